// round 6
// baseline (speedup 1.0000x reference)
#include <cuda_runtime.h>
#include <cuda_bf16.h>
#include <cstdint>
#include <math.h>

// ---------------- problem constants ----------------
#define N_TOT   65536      // B*H*W
#define K_CB    512
#define C_DIM   64
#define B_DIM   64
#define HW      1024
#define MT      64         // rows per CTA
#define DTHREADS 256

// output layout (floats), concatenation of the reference tuple
#define Q_OFF     0ULL
#define LOSS_OFF  4194304ULL
#define PERP_OFF  4194368ULL
#define ENC_OFF   4194369ULL
#define EIDX_OFF  37748801ULL
#define DIST_OFF  37814337ULL
#define OUT_TOTAL 71368769

// ---------------- smem layout (bytes) ----------------
// bf16 tiles, row stride 72 halves (144B): 16B-aligned, ldmatrix-friendly
#define SROW    72
#define XSROW   65                     // fp32 x tile stride (bank-conflict-free column reads)
#define SM_AH   0                      // A_h[64][72]   9216 B
#define SM_AL   9216                   // A_l[64][72]   9216 B
#define SM_BH   18432                  // B_h[512][72]  73728 B
#define SM_BL   92160                  // B_l[512][72]  73728 B
#define SM_XS   165888                 // float xs[64][65] 16640 B
#define SM_WN   182528                 // float wnorm[512]
#define SM_XN   184576                 // float xnorm[64]
#define SM_CANB 184832                 // float candb[64][2][2] (row, wc, rank)
#define SM_CANI 185856                 // int   candi[64][2][2]
#define SM_IDX  186880                 // int sm_idx[64]
#define SM_RED  187136                 // float red[256]
#define SMEM_D  188160

__device__ float g_lpart[1024];
__device__ int   g_hist [K_CB];       // zero at load; vq_finish re-zeroes each launch

// ---------------- ptx helpers ----------------
__device__ __forceinline__ uint32_t smem_u32(const void* p) {
    uint32_t a;
    asm("{ .reg .u64 t; cvta.to.shared.u64 t, %1; cvt.u32.u64 %0, t; }" : "=r"(a) : "l"(p));
    return a;
}

#define LDSM_X4(r0, r1, r2, r3, addr)                                            \
    asm volatile("ldmatrix.sync.aligned.m8n8.x4.shared.b16 {%0,%1,%2,%3}, [%4];" \
        : "=r"(r0), "=r"(r1), "=r"(r2), "=r"(r3) : "r"(addr))

__device__ __forceinline__ void mma_bf16(float* d, const uint32_t* a,
                                         uint32_t b0, uint32_t b1) {
    asm volatile(
        "mma.sync.aligned.m16n8k16.row.col.f32.bf16.bf16.f32 "
        "{%0,%1,%2,%3}, {%4,%5,%6,%7}, {%8,%9}, {%0,%1,%2,%3};"
        : "+f"(d[0]), "+f"(d[1]), "+f"(d[2]), "+f"(d[3])
        : "r"(a[0]), "r"(a[1]), "r"(a[2]), "r"(a[3]), "r"(b0), "r"(b1));
}

// top-2 update with lexicographic (d, idx) order; strict '<' keeps lowest index
__device__ __forceinline__ void top2_upd(float d, int i,
                                         float &b1, int &i1, float &b2, int &i2) {
    if (d < b1) { b2 = b1; i2 = i1; b1 = d; i1 = i; }
    else if (d < b2) { b2 = d; i2 = i; }
}
__device__ __forceinline__ int lexlt(float d, int i, float D, int I) {
    return (d < D) || (d == D && i < I);
}

// ---------------- kernel 1: distances + argmin(+rescue) + all elementwise outputs ----------------
extern "C" __global__ void __launch_bounds__(DTHREADS, 1)
vq_main(const float* __restrict__ inputs, const float* __restrict__ weight,
        float* __restrict__ out)
{
    extern __shared__ char smc[];
    __nv_bfloat16* Ah = (__nv_bfloat16*)(smc + SM_AH);
    __nv_bfloat16* Al = (__nv_bfloat16*)(smc + SM_AL);
    float* xs    = (float*)(smc + SM_XS);
    float* wnorm = (float*)(smc + SM_WN);
    float* xnorm = (float*)(smc + SM_XN);
    float* candb = (float*)(smc + SM_CANB);
    int*   candi = (int*)  (smc + SM_CANI);
    int*   smidx = (int*)  (smc + SM_IDX);
    float* red   = (float*)(smc + SM_RED);

    const uint32_t sb = smem_u32(smc);
    const int tid  = threadIdx.x;
    const int wid  = tid >> 5;
    const int lane = tid & 31;
    const int n0   = blockIdx.x * MT;        // 64-aligned -> single image
    const int bimg = n0 >> 10;
    const int p0   = n0 & (HW - 1);

    // ---- prologue: x tile -> fp32 smem + bf16 hi/lo ----
    const float* xb = inputs + (size_t)bimg * (C_DIM * HW) + p0;
    for (int i = tid; i < C_DIM * MT; i += DTHREADS) {
        int c = i >> 6, r = i & 63;                       // coalesced over r
        float x = xb[(size_t)c * HW + r];
        __nv_bfloat16 h = __float2bfloat16(x);
        float l = x - __bfloat162float(h);
        Ah[r * SROW + c] = h;
        Al[r * SROW + c] = __float2bfloat16(l);
        xs[r * XSROW + c] = x;
    }
    // ---- codebook [512][64] -> bf16 hi/lo (packed u32 stores) ----
    {
        const float2* w2 = (const float2*)weight;
        uint32_t* BHu = (uint32_t*)(smc + SM_BH);
        uint32_t* BLu = (uint32_t*)(smc + SM_BL);
        for (int i = tid; i < K_CB * 32; i += DTHREADS) {
            int n = i >> 5, cp = i & 31;
            float2 w = w2[i];
            __nv_bfloat162 h2 = __floats2bfloat162_rn(w.x, w.y);
            float l0 = w.x - __low2float(h2);
            float l1 = w.y - __high2float(h2);
            __nv_bfloat162 l2 = __floats2bfloat162_rn(l0, l1);
            BHu[n * (SROW / 2) + cp] = *(uint32_t*)&h2;
            BLu[n * (SROW / 2) + cp] = *(uint32_t*)&l2;
        }
    }
    // ---- norms (sequential fmaf: reference-class rounding) ----
    {
        float s0 = 0.f, s1 = 0.f;
        const float* wr0 = weight + tid * C_DIM;
        const float* wr1 = weight + (tid + 256) * C_DIM;
        #pragma unroll
        for (int c = 0; c < C_DIM; c++) {
            float w0 = wr0[c]; s0 = fmaf(w0, w0, s0);
            float w1 = wr1[c]; s1 = fmaf(w1, w1, s1);
        }
        wnorm[tid] = s0; wnorm[tid + 256] = s1;
    }
    __syncthreads();
    if (tid < MT) {
        float s = 0.f;
        const float* xr = xs + tid * XSROW;
        #pragma unroll
        for (int c = 0; c < C_DIM; c++) { float x = xr[c]; s = fmaf(x, x, s); }
        xnorm[tid] = s;
    }
    __syncthreads();

    // ---- warp tiling: wr = rows wr*16..+15, wc = cols wc*256..+255 ----
    const int wr = wid & 3, wc = wid >> 2;
    const int rbase = wr * 16;

    // preload A fragments
    uint32_t ah[4][4], al[4][4];
    {
        const int arow = rbase + (lane & 7) + 8 * ((lane >> 3) & 1);
        const int koff = 8 * (lane >> 4);
        uint32_t base_h = sb + SM_AH + arow * (SROW * 2) + koff * 2;
        uint32_t base_l = sb + SM_AL + arow * (SROW * 2) + koff * 2;
        #pragma unroll
        for (int ks = 0; ks < 4; ks++) {
            LDSM_X4(ah[ks][0], ah[ks][1], ah[ks][2], ah[ks][3], base_h + ks * 32);
            LDSM_X4(al[ks][0], al[ks][1], al[ks][2], al[ks][3], base_l + ks * 32);
        }
    }

    const int r0 = rbase + (lane >> 2);
    const int r1 = r0 + 8;
    const float xn0 = xnorm[r0], xn1 = xnorm[r1];
    const float INF = __int_as_float(0x7f800000);
    float b10 = INF, b20 = INF, b11 = INF, b21 = INF;
    int   i10 = 0,   i20 = 0,   i11 = 0,   i21 = 0;

    float* orow0 = out + DIST_OFF + (size_t)(n0 + r0) * K_CB;
    float* orow1 = out + DIST_OFF + (size_t)(n0 + r1) * K_CB;

    const int bln = (lane & 7) + 8 * (lane >> 4);
    const int blk = 8 * ((lane >> 3) & 1);

    for (int chunk = 0; chunk < 4; chunk++) {
        const int nb = wc * 256 + chunk * 64;
        float acc[8][4];
        #pragma unroll
        for (int s = 0; s < 8; s++)
            #pragma unroll
            for (int j = 0; j < 4; j++) acc[s][j] = 0.f;

        #pragma unroll
        for (int s2 = 0; s2 < 4; s2++) {
            const int nrow = nb + 16 * s2 + bln;
            uint32_t bh_base = sb + SM_BH + nrow * (SROW * 2) + blk * 2;
            uint32_t bl_base = sb + SM_BL + nrow * (SROW * 2) + blk * 2;
            #pragma unroll
            for (int ks = 0; ks < 4; ks++) {
                uint32_t h0, h1, h2, h3, l0, l1, l2, l3;
                LDSM_X4(h0, h1, h2, h3, bh_base + ks * 32);
                LDSM_X4(l0, l1, l2, l3, bl_base + ks * 32);
                mma_bf16(acc[2 * s2],     ah[ks], h0, h1);   // xh*eh
                mma_bf16(acc[2 * s2 + 1], ah[ks], h2, h3);
                mma_bf16(acc[2 * s2],     al[ks], h0, h1);   // xl*eh
                mma_bf16(acc[2 * s2 + 1], al[ks], h2, h3);
                mma_bf16(acc[2 * s2],     ah[ks], l0, l1);   // xh*el
                mma_bf16(acc[2 * s2 + 1], ah[ks], l2, l3);
            }
        }

        #pragma unroll
        for (int s = 0; s < 8; s++) {
            const int col = nb + 8 * s + 2 * (lane & 3);
            const float wn0 = wnorm[col], wn1 = wnorm[col + 1];
            float d00 = (xn0 + wn0) - 2.0f * acc[s][0];
            float d01 = (xn0 + wn1) - 2.0f * acc[s][1];
            float d10 = (xn1 + wn0) - 2.0f * acc[s][2];
            float d11 = (xn1 + wn1) - 2.0f * acc[s][3];
            orow0[col] = d00; orow0[col + 1] = d01;
            orow1[col] = d10; orow1[col + 1] = d11;
            top2_upd(d00, col,     b10, i10, b20, i20);
            top2_upd(d01, col + 1, b10, i10, b20, i20);
            top2_upd(d10, col,     b11, i11, b21, i21);
            top2_upd(d11, col + 1, b11, i11, b21, i21);
        }
    }

    // merge top-2 among the 4 lanes sharing each row (xor 1, 2)
    #pragma unroll
    for (int off = 1; off <= 2; off <<= 1) {
        float o1 = __shfl_xor_sync(0xffffffffu, b10, off);
        int   q1 = __shfl_xor_sync(0xffffffffu, i10, off);
        float o2 = __shfl_xor_sync(0xffffffffu, b20, off);
        int   q2 = __shfl_xor_sync(0xffffffffu, i20, off);
        if (lexlt(o1, q1, b10, i10)) {
            float t = b10; int ti = i10;
            b10 = o1; i10 = q1;
            if (lexlt(o2, q2, t, ti)) { b20 = o2; i20 = q2; } else { b20 = t; i20 = ti; }
        } else {
            if (lexlt(o1, q1, b20, i20)) { b20 = o1; i20 = q1; }
        }
        o1 = __shfl_xor_sync(0xffffffffu, b11, off);
        q1 = __shfl_xor_sync(0xffffffffu, i11, off);
        o2 = __shfl_xor_sync(0xffffffffu, b21, off);
        q2 = __shfl_xor_sync(0xffffffffu, i21, off);
        if (lexlt(o1, q1, b11, i11)) {
            float t = b11; int ti = i11;
            b11 = o1; i11 = q1;
            if (lexlt(o2, q2, t, ti)) { b21 = o2; i21 = q2; } else { b21 = t; i21 = ti; }
        } else {
            if (lexlt(o1, q1, b21, i21)) { b21 = o1; i21 = q1; }
        }
    }
    if ((lane & 3) == 0) {
        candb[(r0 * 2 + wc) * 2]     = b10;  candi[(r0 * 2 + wc) * 2]     = i10;
        candb[(r0 * 2 + wc) * 2 + 1] = b20;  candi[(r0 * 2 + wc) * 2 + 1] = i20;
        candb[(r1 * 2 + wc) * 2]     = b11;  candi[(r1 * 2 + wc) * 2]     = i11;
        candb[(r1 * 2 + wc) * 2 + 1] = b21;  candi[(r1 * 2 + wc) * 2 + 1] = i21;
    }
    __syncthreads();

    // ---- rescue: exact fp32 recompute of the <=4 candidates per row ----
    if (tid < MT) {
        const int row = tid;
        const float xn = xnorm[row];
        const float* xr = xs + row * XSROW;
        float bd = INF; int bi = 0x7fffffff;
        #pragma unroll
        for (int cnd = 0; cnd < 4; cnd++) {
            int k = candi[row * 4 + cnd];
            const float* wr = weight + (size_t)k * C_DIM;
            float z = 0.f;
            #pragma unroll
            for (int c = 0; c < C_DIM; c++) z = fmaf(xr[c], wr[c], z);
            float d = (xn + wnorm[k]) - 2.0f * z;      // reference rounding
            if (lexlt(d, k, bd, bi)) { bd = d; bi = k; }
        }
        smidx[row] = bi;
        out[EIDX_OFF + (size_t)(n0 + row)] = (float)bi;
        atomicAdd(&g_hist[bi], 1);                     // int atomics: order-independent
    }
    __syncthreads();

    // encodings one-hot rows
    {
        float* ebase = out + ENC_OFF + (size_t)n0 * K_CB;
        #pragma unroll 8
        for (int i = tid; i < MT * K_CB; i += DTHREADS) {
            int row = i >> 9, k = i & 511;
            ebase[i] = (k == smidx[row]) ? 1.0f : 0.0f;
        }
    }

    // q_out (straight-through: x + (q - x)) + fused loss partial
    float* qbase = out + (size_t)bimg * (C_DIM * HW) + p0;
    float s = 0.f;
    #pragma unroll 2
    for (int i = tid; i < C_DIM * MT; i += DTHREADS) {
        int c = i >> 6, p = i & 63;
        float x = xs[p * XSROW + c];
        float q = weight[smidx[p] * C_DIM + c];
        float d = q - x;
        qbase[(size_t)c * HW + p] = x + d;
        s = fmaf(d, d, s);
    }
    red[tid] = s;
    __syncthreads();
    #pragma unroll
    for (int off = 128; off > 0; off >>= 1) {
        if (tid < off) red[tid] += red[tid + off];
        __syncthreads();
    }
    if (tid == 0) g_lpart[blockIdx.x] = red[0];
}

// ---------------- kernel 2: loss + perplexity; re-zero hist ----------------
extern "C" __global__ void vq_finish(float* __restrict__ out)
{
    __shared__ float red[K_CB];
    const int tid = threadIdx.x;

    if (tid < B_DIM) {
        float s = 0.f;
        #pragma unroll
        for (int j = 0; j < 16; j++) s += g_lpart[tid * 16 + j];   // fixed order
        out[LOSS_OFF + tid] = 1.25f * (s * (1.0f / 65536.0f));
    }

    int h = g_hist[tid];
    g_hist[tid] = 0;                                   // restore invariant
    float p = (float)h * (1.0f / 65536.0f);
    red[tid] = -p * logf(p + 1e-10f);
    __syncthreads();
    #pragma unroll
    for (int off = 256; off > 0; off >>= 1) {
        if (tid < off) red[tid] += red[tid + off];
        __syncthreads();
    }
    if (tid == 0) out[PERP_OFF] = expf(red[0]);
}

// ---------------- launch ----------------
extern "C" void kernel_launch(void* const* d_in, const int* in_sizes, int n_in,
                              void* d_out, int out_size)
{
    const float* inputs = (const float*)d_in[0];
    const float* weight = (const float*)d_in[1];
    float* out = (float*)d_out;

    if (out_size != OUT_TOTAL) return;

    cudaFuncSetAttribute(vq_main, cudaFuncAttributeMaxDynamicSharedMemorySize, SMEM_D);

    vq_main  <<<N_TOT / MT, DTHREADS, SMEM_D>>>(inputs, weight, out);
    vq_finish<<<1, K_CB>>>(out);
}

// round 7
// speedup vs baseline: 1.9193x; 1.9193x over previous
#include <cuda_runtime.h>
#include <math.h>

// ---------------- problem constants ----------------
#define N_TOT   65536      // B*H*W
#define K_CB    512
#define C_DIM   64
#define B_DIM   64
#define HW      1024

#define TM      64         // rows per CTA
#define THREADS 512
#define WROW    514        // wT row stride (floats): even (8B align), 2-way STS on transpose only

// output layout (floats), concatenation of the reference tuple
#define Q_OFF     0ULL                       // [64,64,32,32] = 4194304
#define LOSS_OFF  4194304ULL                 // [64]
#define PERP_OFF  4194368ULL                 // [1]
#define ENC_OFF   4194369ULL                 // [65536,512] = 33554432
#define EIDX_OFF  37748801ULL                // [64,1024]   = 65536
#define DIST_OFF  37814337ULL                // [65536,512] = 33554432
#define OUT_TOTAL 71368769

// smem layout (float indices). wT has 65 rows: row 64 is a prefetch pad (read-garbage).
#define SM_WT   0
#define SM_XSD  33412                  // 16B-aligned; xsd pairs {x,x}: 64*64 float2 = 8192 floats
#define SM_WN   (SM_XSD + 8192)       // wnorm[512]
#define SM_XN   (SM_WN + 512)         // xnorm[64]
#define SM_SIDX (SM_XN + 64)          // int sidx[64]
#define SM_CANB (SM_SIDX + 64)        // float candb[128]
#define SM_CANI (SM_CANB + 128)       // int candi[128]
#define SM_RED  (SM_CANI + 128)       // float red[512]
#define SM_TOTF (SM_RED + 512)
#define SMEM_BYTES (SM_TOTF * 4)      // ~172 KB -> 1 CTA/SM (opt-in)

__device__ float g_lpart[1024];
__device__ int   g_hist [K_CB];       // zero at load; vq_finish re-zeroes each launch

typedef unsigned long long ull;

// ---------------- f32x2 helpers ----------------
__device__ __forceinline__ void fma2(ull &d, ull a, ull b) {
    asm("fma.rn.f32x2 %0, %1, %2, %3;" : "=l"(d) : "l"(a), "l"(b), "l"(d));
}
__device__ __forceinline__ void unpack2(ull v, float &lo, float &hi) {
    asm("mov.b64 {%0, %1}, %2;" : "=f"(lo), "=f"(hi) : "l"(v));
}

// ---------------- main kernel: distances + argmin + all outputs ----------------
extern "C" __global__ void __launch_bounds__(THREADS, 1)
vq_main(const float* __restrict__ inputs, const float* __restrict__ weight,
        float* __restrict__ out)
{
    extern __shared__ float smem[];
    float* wT    = smem + SM_WT;      // wT[c][k], row stride WROW, 65 rows (last = pad)
    float* xsd   = smem + SM_XSD;     // {x,x} pairs, pair index c*64 + r
    float* wnorm = smem + SM_WN;
    float* xnorm = smem + SM_XN;
    int*   sidx  = (int*)(smem + SM_SIDX);
    float* candb = smem + SM_CANB;
    int*   candi = (int*)(smem + SM_CANI);
    float* red   = smem + SM_RED;

    const int tid = threadIdx.x;
    const int n0  = blockIdx.x * TM;        // 64-aligned -> single batch image
    const int b   = n0 >> 10;
    const int p0  = n0 & (HW - 1);

    // load weight [K,C] row-major -> transposed smem (coalesced gmem; 2-way STS)
    for (int i = tid; i < K_CB * C_DIM; i += THREADS) {
        int k = i >> 6, c = i & 63;
        wT[c * WROW + k] = weight[i];
    }
    // pad row 64 of wT deterministically (prefetch target; values unused)
    for (int k = tid; k < K_CB; k += THREADS) wT[64 * WROW + k] = 0.f;

    // load x tile duplicated: pair (c*64 + r) = {x, x}
    const float* xbase = inputs + (size_t)b * (C_DIM * HW) + p0;
    for (int i = tid; i < C_DIM * TM; i += THREADS) {
        int c = i >> 6, r = i & 63;
        float v = xbase[(size_t)c * HW + r];
        ((float2*)xsd)[c * 64 + r] = make_float2(v, v);
    }
    __syncthreads();

    // wnorm[k] = sum_c wT[c][k]^2 ; xnorm[r] = sum_c x^2   (sequential fmaf rounding)
    {
        float s = 0.f;
        #pragma unroll
        for (int c = 0; c < C_DIM; c++) { float w = wT[c * WROW + tid]; s = fmaf(w, w, s); }
        wnorm[tid] = s;
    }
    if (tid < TM) {
        float s = 0.f;
        #pragma unroll
        for (int c = 0; c < C_DIM; c++) { float x = xsd[(c * 64 + tid) * 2]; s = fmaf(x, x, s); }
        xnorm[tid] = s;
    }
    __syncthreads();

    // thread tile: 8 rows x 8 codes. warp w: rowg = w>>1 (rows rowg*8..+7), kg = w&1
    const int warp = tid >> 5;
    const int lane = tid & 31;
    const int rowg = warp >> 1;
    const int kg   = warp & 1;
    const int kb   = kg * 256 + 2 * lane;   // codes kb + 64*jj + {0,1}, jj=0..3

    ull acc[8][4];
    #pragma unroll
    for (int r = 0; r < 8; r++)
        #pragma unroll
        for (int j = 0; j < 4; j++) acc[r][j] = 0ULL;

    const ulonglong2* arow = (const ulonglong2*)xsd + rowg * 4;   // 8 rows = 4 ull2 per c
    const ull* bbase = (const ull*)(wT + kb);                     // + c*(WROW/2) + 32*j

    // ---- software-pipelined mainloop: double-buffered B, 2 c-steps per body ----
    ull bb0[4], bb1[4], aa[8];
    #pragma unroll
    for (int j = 0; j < 4; j++) bb0[j] = bbase[32 * j];           // c = 0

    #pragma unroll 4
    for (int c2 = 0; c2 < 32; c2++) {
        const int c = 2 * c2;
        // prefetch B(c+1)
        const ull* bp1 = bbase + (size_t)(c + 1) * (WROW / 2);
        #pragma unroll
        for (int j = 0; j < 4; j++) bb1[j] = bp1[32 * j];
        // A(c) broadcast (duplicated pairs)
        #pragma unroll
        for (int i = 0; i < 4; i++) {
            ulonglong2 v = arow[c * 32 + i];
            aa[2 * i] = v.x; aa[2 * i + 1] = v.y;
        }
        #pragma unroll
        for (int r = 0; r < 8; r++)
            #pragma unroll
            for (int j = 0; j < 4; j++) fma2(acc[r][j], aa[r], bb0[j]);
        // prefetch B(c+2) (c2==31 reads pad row 64 -> harmless)
        const ull* bp2 = bbase + (size_t)(c + 2) * (WROW / 2);
        #pragma unroll
        for (int j = 0; j < 4; j++) bb0[j] = bp2[32 * j];
        // A(c+1)
        #pragma unroll
        for (int i = 0; i < 4; i++) {
            ulonglong2 v = arow[(c + 1) * 32 + i];
            aa[2 * i] = v.x; aa[2 * i + 1] = v.y;
        }
        #pragma unroll
        for (int r = 0; r < 8; r++)
            #pragma unroll
            for (int j = 0; j < 4; j++) fma2(acc[r][j], aa[r], bb1[j]);
    }

    // ---- epilogue: distances (reference rounding), per-warp argmin, candidates ----
    const float INF = __int_as_float(0x7f800000);
    #pragma unroll
    for (int r = 0; r < 8; r++) {
        const int row = rowg * 8 + r;
        const int n   = n0 + row;
        const float xn = xnorm[row];

        float best = INF; int bidx = 0;
        float* dptr = out + DIST_OFF + (size_t)n * K_CB + kb;
        #pragma unroll
        for (int j = 0; j < 4; j++) {
            float zlo, zhi; unpack2(acc[r][j], zlo, zhi);
            const int k0 = kb + 64 * j;
            float dlo = (xn + wnorm[k0])     - 2.0f * zlo;
            float dhi = (xn + wnorm[k0 + 1]) - 2.0f * zhi;
            dptr[64 * j]     = dlo;      // lane stride 8B -> coalesced STG.64
            dptr[64 * j + 1] = dhi;
            if (dlo < best) { best = dlo; bidx = k0; }      // ascending k, strict '<'
            if (dhi < best) { best = dhi; bidx = k0 + 1; }  // -> lowest index on ties
        }
        #pragma unroll
        for (int off = 16; off > 0; off >>= 1) {
            float ob = __shfl_xor_sync(0xffffffffu, best, off);
            int   oi = __shfl_xor_sync(0xffffffffu, bidx, off);
            if (ob < best || (ob == best && oi < bidx)) { best = ob; bidx = oi; }
        }
        if (lane == 0) { candb[row * 2 + kg] = best; candi[row * 2 + kg] = bidx; }
    }
    __syncthreads();

    // combine the two code-half candidates per row (half0 indices all lower)
    if (tid < TM) {
        float b0 = candb[tid * 2], b1 = candb[tid * 2 + 1];
        int   i0 = candi[tid * 2], i1 = candi[tid * 2 + 1];
        int bi = (b1 < b0) ? i1 : i0;
        sidx[tid] = bi;
        out[EIDX_OFF + (size_t)(n0 + tid)] = (float)bi;
        atomicAdd(&g_hist[bi], 1);              // int atomics: order-independent
    }
    __syncthreads();

    // encodings: full one-hot rows
    {
        float* ebase = out + ENC_OFF + (size_t)n0 * K_CB;
        #pragma unroll 4
        for (int i = tid; i < TM * K_CB; i += THREADS) {
            int row = i >> 9, k = i & 511;
            ebase[i] = (k == sidx[row]) ? 1.0f : 0.0f;
        }
    }

    // q_out (straight-through: x + (q - x)) + fused loss partial
    float* qbase = out + (size_t)b * (C_DIM * HW) + p0;
    float s = 0.f;
    #pragma unroll 2
    for (int i = tid; i < C_DIM * TM; i += THREADS) {
        int c = i >> 6, p = i & 63;
        float x = xsd[(c * 64 + p) * 2];
        float q = wT[c * WROW + sidx[p]];
        float d = q - x;
        qbase[(size_t)c * HW + p] = x + d;
        s = fmaf(d, d, s);
    }
    red[tid] = s;
    __syncthreads();
    #pragma unroll
    for (int off = 256; off > 0; off >>= 1) {
        if (tid < off) red[tid] += red[tid + off];
        __syncthreads();
    }
    if (tid == 0) g_lpart[blockIdx.x] = red[0];
}

// ---------------- finish kernel: loss + perplexity; re-zero hist ----------------
extern "C" __global__ void vq_finish(float* __restrict__ out)
{
    __shared__ float red[K_CB];
    const int tid = threadIdx.x;

    if (tid < B_DIM) {
        float s = 0.f;
        #pragma unroll
        for (int j = 0; j < 16; j++) s += g_lpart[tid * 16 + j];   // fixed order
        out[LOSS_OFF + tid] = 1.25f * (s * (1.0f / 65536.0f));
    }

    int h = g_hist[tid];
    g_hist[tid] = 0;                            // restore zero-at-entry invariant
    float p = (float)h * (1.0f / 65536.0f);
    red[tid] = -p * logf(p + 1e-10f);
    __syncthreads();
    #pragma unroll
    for (int off = 256; off > 0; off >>= 1) {
        if (tid < off) red[tid] += red[tid + off];
        __syncthreads();
    }
    if (tid == 0) out[PERP_OFF] = expf(red[0]);
}

// ---------------- launch ----------------
extern "C" void kernel_launch(void* const* d_in, const int* in_sizes, int n_in,
                              void* d_out, int out_size)
{
    const float* inputs = (const float*)d_in[0];
    const float* weight = (const float*)d_in[1];
    float* out = (float*)d_out;

    if (out_size != OUT_TOTAL) return;

    cudaFuncSetAttribute(vq_main, cudaFuncAttributeMaxDynamicSharedMemorySize, SMEM_BYTES);

    vq_main  <<<N_TOT / TM, THREADS, SMEM_BYTES>>>(inputs, weight, out);
    vq_finish<<<1, K_CB>>>(out);
}

// round 8
// speedup vs baseline: 2.7539x; 1.4349x over previous
#include <cuda_runtime.h>
#include <math.h>
#include <cstdint>

// ---------------- problem constants ----------------
#define N_TOT   65536      // B*H*W
#define K_CB    512
#define C_DIM   64
#define B_DIM   64
#define HW      1024

#define TM      64         // rows per tile
#define THREADS 512
#define NTILES  1024
#define NCTAS   152        // GB300 SM count; persistent 1 CTA/SM
#define WROW    514        // wT row stride (floats)

// output layout (floats), concatenation of the reference tuple
#define Q_OFF     0ULL
#define LOSS_OFF  4194304ULL
#define PERP_OFF  4194368ULL
#define ENC_OFF   4194369ULL
#define EIDX_OFF  37748801ULL
#define DIST_OFF  37814337ULL
#define OUT_TOTAL 71368769

// smem layout (float indices). wT has 65 rows: row 64 is a prefetch pad.
#define SM_WT   0                      // 65*514 = 33410 -> pad 33412
#define SM_XS   33412                  // xs[2][64*64] raw floats (double buffer)
#define SM_WN   (SM_XS + 8192)         // wnorm[512]
#define SM_XN   (SM_WN + 512)          // xnorm[64]
#define SM_SIDX (SM_XN + 64)           // int sidx[64]
#define SM_CANB (SM_SIDX + 64)         // float candb[128]
#define SM_CANI (SM_CANB + 128)        // int candi[128]
#define SM_RED  (SM_CANI + 128)        // float red[512]
#define SM_TOTF (SM_RED + 512)
#define SMEM_BYTES (SM_TOTF * 4)       // ~172 KB -> 1 CTA/SM

__device__ float g_lpart[NTILES];
__device__ int   g_hist [K_CB];        // zero at load; last CTA re-zeroes each launch
__device__ int   g_done;               // arrival ticket; last CTA resets

typedef unsigned long long ull;

// ---------------- helpers ----------------
__device__ __forceinline__ ull pack2(float x) {
    ull r; asm("mov.b64 %0, {%1, %1};" : "=l"(r) : "f"(x)); return r;
}
__device__ __forceinline__ void fma2(ull &d, ull a, ull b) {
    asm("fma.rn.f32x2 %0, %1, %2, %3;" : "=l"(d) : "l"(a), "l"(b), "l"(d));
}
__device__ __forceinline__ void unpack2(ull v, float &lo, float &hi) {
    asm("mov.b64 {%0, %1}, %2;" : "=f"(lo), "=f"(hi) : "l"(v));
}
__device__ __forceinline__ uint32_t smem_u32(const void* p) {
    uint32_t a;
    asm("{ .reg .u64 t; cvta.to.shared.u64 t, %1; cvt.u32.u64 %0, t; }" : "=r"(a) : "l"(p));
    return a;
}
#define CP_ASYNC16(sa, gp) asm volatile("cp.async.cg.shared.global [%0], [%1], 16;" :: "r"(sa), "l"(gp))
#define CP_COMMIT()        asm volatile("cp.async.commit_group;" ::: "memory")
#define CP_WAIT1()         asm volatile("cp.async.wait_group 1;" ::: "memory")
#define CP_WAIT0()         asm volatile("cp.async.wait_group 0;" ::: "memory")

// ---------------- single persistent kernel ----------------
extern "C" __global__ void __launch_bounds__(THREADS, 1)
vq_all(const float* __restrict__ inputs, const float* __restrict__ weight,
       float* __restrict__ out)
{
    extern __shared__ float smem[];
    float* wT    = smem + SM_WT;
    float* wnorm = smem + SM_WN;
    float* xnorm = smem + SM_XN;
    int*   sidx  = (int*)(smem + SM_SIDX);
    float* candb = smem + SM_CANB;
    int*   candi = (int*)(smem + SM_CANI);
    float* red   = smem + SM_RED;

    const uint32_t xs_sa = smem_u32(smem + SM_XS);
    const int tid  = threadIdx.x;
    const int warp = tid >> 5;
    const int lane = tid & 31;
    const int rowg = warp >> 1;
    const int kg   = warp & 1;
    const int kb   = kg * 256 + 2 * lane;     // codes kb + 64*jj + {0,1}
    const int cta  = blockIdx.x;

    // ---- prefetch first x tile (tile index = cta) into buffer 0 ----
    {
        const int t0 = cta;
        const float* src = inputs + (size_t)(t0 >> 4) * (C_DIM * HW) + (t0 & 15) * 64;
        for (int i = tid; i < 1024; i += THREADS) {
            int c = i >> 4, ro = (i & 15) * 4;
            CP_ASYNC16(xs_sa + (uint32_t)(c * 64 + ro) * 4, src + (size_t)c * HW + ro);
        }
        CP_COMMIT();
    }

    // ---- one-time: weight transpose + pad + wnorm ----
    for (int i = tid; i < K_CB * C_DIM; i += THREADS) {
        int k = i >> 6, c = i & 63;
        wT[c * WROW + k] = weight[i];
    }
    for (int k = tid; k < K_CB; k += THREADS) wT[64 * WROW + k] = 0.f;
    __syncthreads();
    {
        float s = 0.f;
        #pragma unroll
        for (int c = 0; c < C_DIM; c++) { float w = wT[c * WROW + tid]; s = fmaf(w, w, s); }
        wnorm[tid] = s;
    }

    // ---- persistent tile loop ----
    int buf = 0;
    for (int t = cta; t < NTILES; t += NCTAS) {
        // prefetch next tile into the other buffer (clamped -> redundant tile 0)
        {
            int tn = t + NCTAS; if (tn >= NTILES) tn = 0;
            const float* src = inputs + (size_t)(tn >> 4) * (C_DIM * HW) + (tn & 15) * 64;
            uint32_t dst = xs_sa + (uint32_t)((buf ^ 1) * 4096) * 4;
            for (int i = tid; i < 1024; i += THREADS) {
                int c = i >> 4, ro = (i & 15) * 4;
                CP_ASYNC16(dst + (uint32_t)(c * 64 + ro) * 4, src + (size_t)c * HW + ro);
            }
            CP_COMMIT();
        }
        CP_WAIT1();            // oldest group (current buffer) complete
        __syncthreads();

        float* xsb = smem + SM_XS + buf * 4096;   // xs[c][r], r contiguous

        // xnorm for this tile (sequential fmaf rounding; conflict-free reads)
        if (tid < TM) {
            float s = 0.f;
            #pragma unroll
            for (int c = 0; c < C_DIM; c++) { float x = xsb[c * 64 + tid]; s = fmaf(x, x, s); }
            xnorm[tid] = s;
        }
        __syncthreads();

        // ---- mainloop (proven round-2 form): 8 rows x 8 codes per thread ----
        ull acc[8][4];
        #pragma unroll
        for (int r = 0; r < 8; r++)
            #pragma unroll
            for (int j = 0; j < 4; j++) acc[r][j] = 0ULL;

        const float* arow = xsb + rowg * 8;
        const ull* bbase = (const ull*)(wT + kb);

        #pragma unroll 4
        for (int c = 0; c < C_DIM; c++) {
            const float4 a0 = *(const float4*)(arow + c * 64);
            const float4 a1 = *(const float4*)(arow + c * 64 + 4);
            ull aa[8];
            aa[0] = pack2(a0.x); aa[1] = pack2(a0.y); aa[2] = pack2(a0.z); aa[3] = pack2(a0.w);
            aa[4] = pack2(a1.x); aa[5] = pack2(a1.y); aa[6] = pack2(a1.z); aa[7] = pack2(a1.w);
            const ull* bp = bbase + (size_t)c * (WROW / 2);
            ull bb[4];
            #pragma unroll
            for (int j = 0; j < 4; j++) bb[j] = bp[32 * j];
            #pragma unroll
            for (int r = 0; r < 8; r++)
                #pragma unroll
                for (int j = 0; j < 4; j++) fma2(acc[r][j], aa[r], bb[j]);
        }

        const int n0   = t * TM;
        const int bimg = t >> 4;
        const int p0   = (t & 15) * 64;

        // ---- epilogue: distances (reference rounding), warp argmin, candidates ----
        const float INF = __int_as_float(0x7f800000);
        #pragma unroll
        for (int r = 0; r < 8; r++) {
            const int row = rowg * 8 + r;
            const int n   = n0 + row;
            const float xn = xnorm[row];

            float best = INF; int bidx = 0;
            float* dptr = out + DIST_OFF + (size_t)n * K_CB + kb;
            #pragma unroll
            for (int j = 0; j < 4; j++) {
                float zlo, zhi; unpack2(acc[r][j], zlo, zhi);
                const int k0 = kb + 64 * j;
                float dlo = (xn + wnorm[k0])     - 2.0f * zlo;
                float dhi = (xn + wnorm[k0 + 1]) - 2.0f * zhi;
                __stcs(dptr + 64 * j,     dlo);     // streaming stores, coalesced
                __stcs(dptr + 64 * j + 1, dhi);
                if (dlo < best) { best = dlo; bidx = k0; }      // ascending k, strict '<'
                if (dhi < best) { best = dhi; bidx = k0 + 1; }  // -> lowest index on ties
            }
            #pragma unroll
            for (int off = 16; off > 0; off >>= 1) {
                float ob = __shfl_xor_sync(0xffffffffu, best, off);
                int   oi = __shfl_xor_sync(0xffffffffu, bidx, off);
                if (ob < best || (ob == best && oi < bidx)) { best = ob; bidx = oi; }
            }
            if (lane == 0) { candb[row * 2 + kg] = best; candi[row * 2 + kg] = bidx; }
        }
        __syncthreads();

        // combine code-half candidates (half0 indices all lower -> tie keeps half0)
        if (tid < TM) {
            float b0 = candb[tid * 2], b1 = candb[tid * 2 + 1];
            int   i0 = candi[tid * 2], i1 = candi[tid * 2 + 1];
            int bi = (b1 < b0) ? i1 : i0;
            sidx[tid] = bi;
            out[EIDX_OFF + (size_t)(n0 + tid)] = (float)bi;
            atomicAdd(&g_hist[bi], 1);            // int atomics: order-independent
        }
        __syncthreads();

        // encodings one-hot rows
        {
            float* ebase = out + ENC_OFF + (size_t)n0 * K_CB;
            #pragma unroll 4
            for (int i = tid; i < TM * K_CB; i += THREADS) {
                int row = i >> 9, k = i & 511;
                __stcs(ebase + i, (k == sidx[row]) ? 1.0f : 0.0f);
            }
        }

        // q_out (straight-through: x + (q - x)) + fused loss partial
        float* qbase = out + (size_t)bimg * (C_DIM * HW) + p0;
        float s = 0.f;
        #pragma unroll 2
        for (int i = tid; i < C_DIM * TM; i += THREADS) {
            int c = i >> 6, p = i & 63;
            float x = xsb[c * 64 + p];
            float q = wT[c * WROW + sidx[p]];
            float d = q - x;
            __stcs(qbase + (size_t)c * HW + p, x + d);
            s = fmaf(d, d, s);
        }
        red[tid] = s;
        __syncthreads();
        #pragma unroll
        for (int off = 256; off > 0; off >>= 1) {
            if (tid < off) red[tid] += red[tid + off];
            __syncthreads();
        }
        if (tid == 0) g_lpart[t] = red[0];
        __syncthreads();         // protects smem reuse + buffer recycling next iter

        buf ^= 1;
    }
    CP_WAIT0();                  // drain any abandoned prefetch

    // ---- fused finish: last CTA computes loss + perplexity ----
    __shared__ int s_last;
    if (tid == 0) {
        __threadfence();
        int tk = atomicAdd(&g_done, 1);
        s_last = (tk == NCTAS - 1);
    }
    __syncthreads();
    if (s_last) {
        if (tid == 0) g_done = 0;                 // reset for graph replay
        if (tid < B_DIM) {
            float s = 0.f;
            #pragma unroll
            for (int j = 0; j < 16; j++) s += g_lpart[tid * 16 + j];   // fixed order
            out[LOSS_OFF + tid] = 1.25f * (s * (1.0f / 65536.0f));
        }
        int h = g_hist[tid];
        g_hist[tid] = 0;                          // restore zero invariant
        float p = (float)h * (1.0f / 65536.0f);
        red[tid] = -p * logf(p + 1e-10f);
        __syncthreads();
        #pragma unroll
        for (int off = 256; off > 0; off >>= 1) {
            if (tid < off) red[tid] += red[tid + off];
            __syncthreads();
        }
        if (tid == 0) out[PERP_OFF] = expf(red[0]);
    }
}

// ---------------- launch ----------------
extern "C" void kernel_launch(void* const* d_in, const int* in_sizes, int n_in,
                              void* d_out, int out_size)
{
    const float* inputs = (const float*)d_in[0];
    const float* weight = (const float*)d_in[1];
    float* out = (float*)d_out;

    if (out_size != OUT_TOTAL) return;

    cudaFuncSetAttribute(vq_all, cudaFuncAttributeMaxDynamicSharedMemorySize, SMEM_BYTES);

    vq_all<<<NCTAS, THREADS, SMEM_BYTES>>>(inputs, weight, out);
}